// round 15
// baseline (speedup 1.0000x reference)
#include <cuda_runtime.h>
#include <cuda_bf16.h>
#include <cstdint>

// ---------------------------------------------------------------------------
// GNNRepresentationNetwork  B=16, C=16, N=4096 (64x64), D_E=64, D_H=128, D_R=256
// Restructured: stencil/GEMM commute (A(hW) = (Ah)W):
//   embed -> split-frags ; gemm(K) [no smem, no barriers] -> support fp32 ;
//   stencil+bias+relu+split -> frags ; ... ; stencil3+mean -> partials ; readout
// GEMM: mma.sync m16n8k16 bf16, 3-pass split (D = Ah*Bh + Ah*Bl + Al*Bh),
//       operands via __ldg from fragment-ordered global buffers.
// Frag layout per (b, 128n-tile, 64k-chunk): 64 rows x 64 words;
//   word = ((n>>3)*4 + ks)*64 + (n&7)*8 + sidx, sidx = kb<8 ? kb : kb-7
//   word content = pack_bf16(k=kb, k=kb+1)
// ---------------------------------------------------------------------------

#define B_  16
#define N_  4096

typedef unsigned long long u64;

__device__ float    g_sup[B_ * 128 * N_];            // 33.5 MB raw support
__device__ uint32_t g_xh0[B_ * 32 * 2 * 4096];       // frag buffers (hi/lo x2)
__device__ uint32_t g_xl0[B_ * 32 * 2 * 4096];
__device__ uint32_t g_xh1[B_ * 32 * 2 * 4096];
__device__ uint32_t g_xl1[B_ * 32 * 2 * 4096];
__device__ float    g_part[B_ * 32 * 2 * 128];
__device__ uint32_t g_wfh[20480];                    // W frags hi (g1|g2|g3)
__device__ uint32_t g_wfl[20480];                    // W frags lo

__device__ __forceinline__ void fma2(u64& d, u64 a, u64 b) {
    asm("fma.rn.f32x2 %0, %1, %2, %0;" : "+l"(d) : "l"(a), "l"(b));
}
__device__ __forceinline__ u64 pack2(float lo, float hi) {
    u64 r; asm("mov.b64 %0, {%1, %2};" : "=l"(r) : "f"(lo), "f"(hi)); return r;
}
__device__ __forceinline__ float2 unpack2(u64 v) {
    float2 f; asm("mov.b64 {%0, %1}, %2;" : "=f"(f.x), "=f"(f.y) : "l"(v)); return f;
}
__device__ __forceinline__ float recip_deg(int deg) {
    return deg == 4 ? 0.2499999375f : (deg == 3 ? 0.3333332222f : 0.4999997500f);
}
__device__ __forceinline__ uint32_t pack_bf16(__nv_bfloat16 a, __nv_bfloat16 b) {
    return (uint32_t)__bfloat16_as_ushort(a) | ((uint32_t)__bfloat16_as_ushort(b) << 16);
}
__device__ __forceinline__ uint32_t split_pack(float v0, float v1, uint32_t& lo) {
    const __nv_bfloat16 h0 = __float2bfloat16(v0);
    const __nv_bfloat16 h1 = __float2bfloat16(v1);
    lo = pack_bf16(__float2bfloat16(v0 - __bfloat162float(h0)),
                   __float2bfloat16(v1 - __bfloat162float(h1)));
    return pack_bf16(h0, h1);
}
__device__ __forceinline__ void mma_bf16(float* c, const uint32_t* a, uint32_t b0, uint32_t b1) {
    asm volatile(
        "mma.sync.aligned.m16n8k16.row.col.f32.bf16.bf16.f32 "
        "{%0,%1,%2,%3}, {%4,%5,%6,%7}, {%8,%9}, {%0,%1,%2,%3};"
        : "+f"(c[0]), "+f"(c[1]), "+f"(c[2]), "+f"(c[3])
        : "r"(a[0]), "r"(a[1]), "r"(a[2]), "r"(a[3]), "r"(b0), "r"(b1));
}
__device__ __forceinline__ void cp16(uint32_t daddr, const void* g, int sz) {
    asm volatile("cp.async.cg.shared.global [%0], [%1], 16, %2;"
                 :: "r"(daddr), "l"(g), "r"(sz) : "memory");
}
#define CP_COMMIT() asm volatile("cp.async.commit_group;" ::: "memory")
#define CP_WAIT0()  asm volatile("cp.async.wait_group 0;" ::: "memory")

// ---------------------------------------------------------------------------
// Fused embed MLP + wsplit. Blocks [0,512): embed; blocks [512,592): wsplit.
// ---------------------------------------------------------------------------
#define SMEM_EMB 61440

__global__ void __launch_bounds__(256, 3)
embed_ws_kernel(const float* __restrict__ obs,
                const float* __restrict__ w1, const float* __restrict__ b1,
                const float* __restrict__ w2, const float* __restrict__ b2,
                const float* __restrict__ g1w, const float* __restrict__ g2w,
                const float* __restrict__ g3w,
                uint32_t* __restrict__ xh, uint32_t* __restrict__ xl,
                uint32_t* __restrict__ wfh, uint32_t* __restrict__ wfl)
{
    const int tid = threadIdx.x;

    if (blockIdx.x >= 512) {
        // ---- wsplit: A-fragment order [wq(4)][t(2)][ks(4)][lane(32)][j(4)] ----
        const int idx = (blockIdx.x - 512) * 256 + tid;   // 0..20479
        const float* W; int base;
        if (idx < 4096)       { W = g1w; base = 0; }
        else if (idx < 12288) { W = g2w; base = 4096; }
        else                  { W = g3w; base = 12288; }
        const int r = idx - base;
        const int chunk = r >> 12;
        const int w = r & 4095;
        const int lane4 = w & 127, ksI = (w >> 7) & 3, t = (w >> 9) & 1, wq = (w >> 10) & 3;
        const int lane = lane4 >> 2, j = lane4 & 3;
        const int grp = lane >> 2, tig = lane & 3;
        const int d = wq * 32 + t * 16 + grp + (j & 1) * 8;
        const int kg = chunk * 64 + ksI * 16 + tig * 2 + (j >> 1) * 8;
        const float w0 = W[kg * 128 + d];
        const float w1v = W[(kg + 1) * 128 + d];
        uint32_t lo0; const uint32_t hi0 = split_pack(w0, w1v, lo0);
        wfh[idx] = hi0; wfl[idx] = lo0;
        return;
    }

    extern __shared__ __align__(16) float esm[];
    float* Xs  = esm;
    float* W1s = esm + 2048;
    float* W2s = esm + 3072;
    float* Hs  = esm + 7168;
    float* Hstage = esm;                   // [32 d][128 n] reuse after compute

    uint32_t sb;
    asm("{ .reg .u64 t; cvta.to.shared.u64 t, %1; cvt.u32.u64 %0, t; }" : "=r"(sb) : "l"(esm));

    const int tx = tid & 15, ty = tid >> 4;
    const int m0 = blockIdx.x * 128;
    const int b  = m0 >> 12, n0 = m0 & (N_ - 1);
    const int bt = m0 >> 7;                // b*32 + tile
    const float* xb = obs + (size_t)b * 16 * N_ + n0;

    {
        const int i0 = tid, i1 = tid + 256;
        cp16(sb + (uint32_t)(((i0 >> 5) * 128 + (i0 & 31) * 4) * 4),
             reinterpret_cast<const float4*>(xb + (size_t)(i0 >> 5) * N_) + (i0 & 31), 16);
        cp16(sb + (uint32_t)(((i1 >> 5) * 128 + (i1 & 31) * 4) * 4),
             reinterpret_cast<const float4*>(xb + (size_t)(i1 >> 5) * N_) + (i1 & 31), 16);
        cp16(sb + (uint32_t)((2048 + tid * 4) * 4), reinterpret_cast<const float4*>(w1) + tid, 16);
#pragma unroll
        for (int i = 0; i < 4; i++)
            cp16(sb + (uint32_t)((3072 + (i * 256 + tid) * 4) * 4),
                 reinterpret_cast<const float4*>(w2) + i * 256 + tid, 16);
    }
    CP_COMMIT();
    CP_WAIT0();
    __syncthreads();

    // Layer 1 (K=16)
    u64 acc[4][4];
#pragma unroll
    for (int dd = 0; dd < 4; dd++) {
        const float bv = b1[ty * 4 + dd];
        const u64 bp = pack2(bv, bv);
#pragma unroll
        for (int j = 0; j < 4; j++) acc[dd][j] = bp;
    }
#pragma unroll
    for (int k = 0; k < 16; k++) {
        const ulonglong2 a01 = *reinterpret_cast<const ulonglong2*>(&Xs[k * 128 + tx * 8]);
        const ulonglong2 a23 = *reinterpret_cast<const ulonglong2*>(&Xs[k * 128 + tx * 8 + 4]);
        const u64 a[4] = { a01.x, a01.y, a23.x, a23.y };
        const float4 w = *reinterpret_cast<const float4*>(&W1s[k * 64 + ty * 4]);
        const float wv[4] = { w.x, w.y, w.z, w.w };
#pragma unroll
        for (int dd = 0; dd < 4; dd++) {
            const u64 wd = pack2(wv[dd], wv[dd]);
#pragma unroll
            for (int j = 0; j < 4; j++) fma2(acc[dd][j], wd, a[j]);
        }
    }
#pragma unroll
    for (int dd = 0; dd < 4; dd++) {
        float* hr = &Hs[(ty * 4 + dd) * 128 + tx * 8];
#pragma unroll
        for (int j = 0; j < 4; j += 2) {
            const float2 p0 = unpack2(acc[dd][j]), p1 = unpack2(acc[dd][j + 1]);
            float4 o = { fmaxf(p0.x, 0.f), fmaxf(p0.y, 0.f), fmaxf(p1.x, 0.f), fmaxf(p1.y, 0.f) };
            *reinterpret_cast<float4*>(hr + j * 2) = o;
        }
    }
    __syncthreads();

    // Layer 2 (K=64)
    u64 acc2[4][4];
#pragma unroll
    for (int dd = 0; dd < 4; dd++) {
        const float bv = b2[ty * 4 + dd];
        const u64 bp = pack2(bv, bv);
#pragma unroll
        for (int j = 0; j < 4; j++) acc2[dd][j] = bp;
    }
#pragma unroll 4
    for (int k = 0; k < 64; k++) {
        const ulonglong2 a01 = *reinterpret_cast<const ulonglong2*>(&Hs[k * 128 + tx * 8]);
        const ulonglong2 a23 = *reinterpret_cast<const ulonglong2*>(&Hs[k * 128 + tx * 8 + 4]);
        const u64 a[4] = { a01.x, a01.y, a23.x, a23.y };
        const float4 w = *reinterpret_cast<const float4*>(&W2s[k * 64 + ty * 4]);
        const float wv[4] = { w.x, w.y, w.z, w.w };
#pragma unroll
        for (int dd = 0; dd < 4; dd++) {
            const u64 wd = pack2(wv[dd], wv[dd]);
#pragma unroll
            for (int j = 0; j < 4; j++) fma2(acc2[dd][j], wd, a[j]);
        }
    }

    // Epilogue: per d-half, stage relu(h2) fp32 then split into B-fragments.
    const int n_loc = tid >> 1, ksh = tid & 1;
#pragma unroll
    for (int h = 0; h < 2; h++) {
        __syncthreads();
        if ((ty >> 3) == h) {
            const int dl0 = (ty & 7) * 4;
#pragma unroll
            for (int dd = 0; dd < 4; dd++) {
                float* hr = &Hstage[(dl0 + dd) * 128 + tx * 8];
#pragma unroll
                for (int j = 0; j < 4; j++) {
                    const float2 p = unpack2(acc2[dd][j]);
                    hr[j * 2]     = fmaxf(p.x, 0.f);
                    hr[j * 2 + 1] = fmaxf(p.y, 0.f);
                }
            }
        }
        __syncthreads();

        const int ks = h * 2 + ksh;
        uint32_t wh[8], wl[8];
#pragma unroll
        for (int p = 0; p < 8; p++) {
            const float v0 = Hstage[(ksh * 16 + 2 * p) * 128 + n_loc];
            const float v1 = Hstage[(ksh * 16 + 2 * p + 1) * 128 + n_loc];
            const int sidx = (2 * p < 8) ? 2 * p : 2 * p - 7;
            wh[sidx] = split_pack(v0, v1, wl[sidx]);
        }
        const size_t base = (size_t)bt * 4096 + (size_t)(((n_loc >> 3) * 4 + ks) * 64 + (n_loc & 7) * 8);
        uint4 a0 = { wh[0], wh[1], wh[2], wh[3] }, a1 = { wh[4], wh[5], wh[6], wh[7] };
        uint4 c0 = { wl[0], wl[1], wl[2], wl[3] }, c1 = { wl[4], wl[5], wl[6], wl[7] };
        *reinterpret_cast<uint4*>(xh + base)     = a0;
        *reinterpret_cast<uint4*>(xh + base + 4) = a1;
        *reinterpret_cast<uint4*>(xl + base)     = c0;
        *reinterpret_cast<uint4*>(xl + base + 4) = c1;
    }
}

// ---------------------------------------------------------------------------
// GEMM: support[b][128 d][n] = W^T(128xK) * X(Kxn). No smem, no barriers.
// 512 CTAs (b, 128n tile), 8 warps: wq=wid&3 -> 32 d, nh=wid>>2 -> 64 n.
// ---------------------------------------------------------------------------
template <int K>
__global__ void __launch_bounds__(256, 2)
gemm_kernel(const uint32_t* __restrict__ xh, const uint32_t* __restrict__ xl,
            const uint32_t* __restrict__ wfh, const uint32_t* __restrict__ wfl,
            float* __restrict__ sup)
{
    constexpr int NCH = K / 64;
    const int tid = threadIdx.x;
    const int wid = tid >> 5, lane = tid & 31;
    const int grp = lane >> 2, tig = lane & 3;
    const int wq = wid & 3, nh = wid >> 2;
    const int bt = blockIdx.x;
    const int b = bt >> 5, n0 = (bt & 31) * 128;
    const uint32_t* bhp = xh + (size_t)bt * NCH * 4096;
    const uint32_t* blp = xl + (size_t)bt * NCH * 4096;

    float acc[2][8][4];
#pragma unroll
    for (int t = 0; t < 2; t++)
#pragma unroll
        for (int c = 0; c < 8; c++)
#pragma unroll
            for (int j = 0; j < 4; j++) acc[t][c][j] = 0.f;

#pragma unroll
    for (int wg = 0; wg < K / 16; wg++) {
        const int chunk = wg >> 2, ks = wg & 3;
        uint32_t ah[2][4], al[2][4];
#pragma unroll
        for (int t = 0; t < 2; t++) {
            const int fo = chunk * 4096 + ((wq * 2 + t) * 4 + ks) * 128 + lane * 4;
            const uint4 vh = __ldg(reinterpret_cast<const uint4*>(&wfh[fo]));
            const uint4 vl = __ldg(reinterpret_cast<const uint4*>(&wfl[fo]));
            ah[t][0] = vh.x; ah[t][1] = vh.y; ah[t][2] = vh.z; ah[t][3] = vh.w;
            al[t][0] = vl.x; al[t][1] = vl.y; al[t][2] = vl.z; al[t][3] = vl.w;
        }
#pragma unroll
        for (int c = 0; c < 8; c++) {
            const int off = chunk * 4096 + ((nh * 8 + c) * 4 + ks) * 64 + lane * 2;
            const uint2 bh = __ldg(reinterpret_cast<const uint2*>(bhp + off));
            const uint2 bl = __ldg(reinterpret_cast<const uint2*>(blp + off));
            mma_bf16(acc[0][c], ah[0], bh.x, bh.y);
            mma_bf16(acc[0][c], ah[0], bl.x, bl.y);
            mma_bf16(acc[0][c], al[0], bh.x, bh.y);
            mma_bf16(acc[1][c], ah[1], bh.x, bh.y);
            mma_bf16(acc[1][c], ah[1], bl.x, bl.y);
            mma_bf16(acc[1][c], al[1], bh.x, bh.y);
        }
    }

    // Raw fp32 store (bias/relu applied by the stencil pass)
    const int d0 = wq * 32 + grp;
    float* ob = sup + (size_t)b * 128 * N_ + n0;
#pragma unroll
    for (int t = 0; t < 2; t++) {
        float* r0 = ob + (size_t)(d0 + t * 16) * N_;
        float* r1 = r0 + (size_t)8 * N_;
#pragma unroll
        for (int c = 0; c < 8; c++) {
            const int nn = nh * 64 + c * 8 + tig * 2;
            float2 v0 = { acc[t][c][0], acc[t][c][1] };
            float2 v1 = { acc[t][c][2], acc[t][c][3] };
            *reinterpret_cast<float2*>(r0 + nn) = v0;
            *reinterpret_cast<float2*>(r1 + nn) = v1;
        }
    }
}

// ---------------------------------------------------------------------------
// Stencil pass: y = relu(rd*(neighbor sum of support) + s_n*bias)
// non-MEAN: emit split B-fragments for the next GEMM.
// MEAN: warp-reduce y over n, write deterministic partials.
// 512 CTAs (b, tile), 256 thr; thread unit = 2 n x 16 d (one ks group), x2.
// ---------------------------------------------------------------------------
template <bool MEAN>
__global__ void __launch_bounds__(256)
stencil_kernel(const float* __restrict__ sup, const float* __restrict__ bias,
               uint32_t* __restrict__ oh, uint32_t* __restrict__ ol,
               float* __restrict__ part)
{
    const int tid = threadIdx.x;
    const int bt = blockIdx.x;
    const int b = bt >> 5, tile = bt & 31;

#pragma unroll
    for (int i = 0; i < 2; i++) {
        const int u = i * 256 + tid;
        const int n2 = (u & 63) * 2;               // even n within tile
        const int ksg = (u >> 6) & 7;              // 0..7 -> 16-d group
        const int d0 = ksg * 16;
        const int n = tile * 128 + n2;
        const int gi = n >> 6, gj0 = n & 63;
        const bool upv = gi > 0, dnv = gi < 63;
        const int dmv = (upv ? 1 : 0) + (dnv ? 1 : 0);
        const bool l0v = gj0 != 0;                 // left of n2
        const bool r1v = gj0 != 62;                // right of n2+1
        const int dg0 = dmv + (l0v ? 1 : 0) + 1;
        const int dg1 = dmv + 1 + (r1v ? 1 : 0);
        const float rd0 = recip_deg(dg0), rd1 = recip_deg(dg1);
        const float sn0 = (float)dg0 * rd0, sn1 = (float)dg1 * rd1;
        const float* sbp = sup + ((size_t)b * 128 + d0) * N_ + n;

        // Compute y[2 n][16 d]
        float y[2][16];
#pragma unroll
        for (int d = 0; d < 16; d++) {
            const float* row = sbp + (size_t)d * N_;
            const float2 ct = *reinterpret_cast<const float2*>(row);
            float2 up = { 0.f, 0.f }, dn = { 0.f, 0.f };
            if (upv) up = *reinterpret_cast<const float2*>(row - 64);
            if (dnv) dn = *reinterpret_cast<const float2*>(row + 64);
            const float lf = l0v ? row[-1] : 0.f;
            const float rt = r1v ? row[2] : 0.f;
            const float bv = __ldg(&bias[d0 + d]);
            y[0][d] = fmaxf(fmaf(sn0, bv, (up.x + dn.x + lf + ct.y) * rd0), 0.f);
            y[1][d] = fmaxf(fmaf(sn1, bv, (up.y + dn.y + ct.x + rt) * rd1), 0.f);
        }

        if (!MEAN) {
            // Pack into B-fragments: for each n, 8 words pack (d=2p, d=2p+1)
            const int chunk = ksg >> 2, ks2 = ksg & 3;
#pragma unroll
            for (int ni = 0; ni < 2; ni++) {
                uint32_t wh[8], wl[8];
#pragma unroll
                for (int p = 0; p < 8; p++) {
                    const int sidx = (2 * p < 8) ? 2 * p : 2 * p - 7;
                    wh[sidx] = split_pack(y[ni][2 * p], y[ni][2 * p + 1], wl[sidx]);
                }
                const size_t base = ((size_t)bt * 2 + chunk) * 4096
                                  + (size_t)(((n2 >> 3) * 4 + ks2) * 64 + ((n2 + ni) & 7) * 8);
                uint4 h0 = { wh[0], wh[1], wh[2], wh[3] };
                uint4 h1 = { wh[4], wh[5], wh[6], wh[7] };
                uint4 l0 = { wl[0], wl[1], wl[2], wl[3] };
                uint4 l1 = { wl[4], wl[5], wl[6], wl[7] };
                *reinterpret_cast<uint4*>(oh + base)     = h0;
                *reinterpret_cast<uint4*>(oh + base + 4) = h1;
                *reinterpret_cast<uint4*>(ol + base)     = l0;
                *reinterpret_cast<uint4*>(ol + base + 4) = l1;
            }
        } else {
            float sm[16];
#pragma unroll
            for (int d = 0; d < 16; d++) sm[d] = y[0][d] + y[1][d];
#pragma unroll
            for (int d = 0; d < 16; d++) {
                float v = sm[d];
                v += __shfl_xor_sync(0xffffffffu, v, 1);
                v += __shfl_xor_sync(0xffffffffu, v, 2);
                v += __shfl_xor_sync(0xffffffffu, v, 4);
                v += __shfl_xor_sync(0xffffffffu, v, 8);
                v += __shfl_xor_sync(0xffffffffu, v, 16);
                sm[d] = v;
            }
            if ((tid & 31) == 0) {
                const int r = (tid >> 5) & 1;      // n-half within tile
                float* pp = part + ((size_t)bt * 2 + r) * 128 + d0;
#pragma unroll
                for (int d = 0; d < 16; d++) pp[d] = sm[d];
            }
        }
    }
}

// ---------------------------------------------------------------------------
// Readout: g[b] = mean of 64 partials; out = relu(relu(g r1 + b1) r2 + b2)
// ---------------------------------------------------------------------------
__global__ void __launch_bounds__(256)
readout_kernel(const float* __restrict__ part,
               const float* __restrict__ r1w, const float* __restrict__ r1b,
               const float* __restrict__ r2w, const float* __restrict__ r2b,
               float* __restrict__ out)
{
    __shared__ float gs[128];
    __shared__ float ts[256];
    const int b = blockIdx.x, t = threadIdx.x;

    if (t < 128) {
        float s = 0.f;
        const float* p = part + (size_t)b * 64 * 128 + t;
#pragma unroll
        for (int k = 0; k < 64; k++) s += p[k * 128];
        gs[t] = s * (1.0f / (float)N_);
    }
    __syncthreads();

    float a1 = r1b[t];
#pragma unroll 8
    for (int k = 0; k < 128; k++) a1 = fmaf(gs[k], r1w[k * 256 + t], a1);
    ts[t] = fmaxf(a1, 0.f);
    __syncthreads();

    float a2 = r2b[t];
#pragma unroll 8
    for (int k = 0; k < 256; k++) a2 = fmaf(ts[k], r2w[k * 256 + t], a2);
    out[b * 256 + t] = fmaxf(a2, 0.f);
}

// ---------------------------------------------------------------------------
extern "C" void kernel_launch(void* const* d_in, const int* in_sizes, int n_in,
                              void* d_out, int out_size)
{
    const float* obs  = (const float*)d_in[0];
    const float* e1_w = (const float*)d_in[1];
    const float* e1_b = (const float*)d_in[2];
    const float* e2_w = (const float*)d_in[3];
    const float* e2_b = (const float*)d_in[4];
    const float* g1_w = (const float*)d_in[5];
    const float* g1_b = (const float*)d_in[6];
    const float* g2_w = (const float*)d_in[7];
    const float* g2_b = (const float*)d_in[8];
    const float* g3_w = (const float*)d_in[9];
    const float* g3_b = (const float*)d_in[10];
    const float* r1_w = (const float*)d_in[11];
    const float* r1_b = (const float*)d_in[12];
    const float* r2_w = (const float*)d_in[13];
    const float* r2_b = (const float*)d_in[14];
    float* out = (float*)d_out;

    float *sup, *part;
    uint32_t *xh0, *xl0, *xh1, *xl1, *wfh, *wfl;
    cudaGetSymbolAddress((void**)&sup,  g_sup);
    cudaGetSymbolAddress((void**)&part, g_part);
    cudaGetSymbolAddress((void**)&xh0,  g_xh0);
    cudaGetSymbolAddress((void**)&xl0,  g_xl0);
    cudaGetSymbolAddress((void**)&xh1,  g_xh1);
    cudaGetSymbolAddress((void**)&xl1,  g_xl1);
    cudaGetSymbolAddress((void**)&wfh,  g_wfh);
    cudaGetSymbolAddress((void**)&wfl,  g_wfl);

    cudaFuncSetAttribute(embed_ws_kernel, cudaFuncAttributeMaxDynamicSharedMemorySize, SMEM_EMB);

    embed_ws_kernel<<<592, 256, SMEM_EMB>>>(obs, e1_w, e1_b, e2_w, e2_b,
                                            g1_w, g2_w, g3_w, xh0, xl0, wfh, wfl);
    gemm_kernel<64><<<512, 256>>>(xh0, xl0, wfh, wfl, sup);
    stencil_kernel<false><<<512, 256>>>(sup, g1_b, xh1, xl1, nullptr);
    gemm_kernel<128><<<512, 256>>>(xh1, xl1, wfh + 4096, wfl + 4096, sup);
    stencil_kernel<false><<<512, 256>>>(sup, g2_b, xh0, xl0, nullptr);
    gemm_kernel<128><<<512, 256>>>(xh0, xl0, wfh + 12288, wfl + 12288, sup);
    stencil_kernel<true><<<512, 256>>>(sup, g3_b, nullptr, nullptr, part);
    readout_kernel<<<B_, 256>>>(part, r1_w, r1_b, r2_w, r2_b, out);
}

// round 16
// speedup vs baseline: 1.0875x; 1.0875x over previous
#include <cuda_runtime.h>
#include <cuda_bf16.h>
#include <cstdint>

// ---------------------------------------------------------------------------
// GNNRepresentationNetwork  B=16, C=16, N=4096 (64x64), D_E=64, D_H=128, D_R=256
// Split architecture (stencil/GEMM commute: A(hW) = (Ah)W):
//   embed -> split-frags ; gemm(K) [no smem/barriers] -> support fp32 ;
//   stencil+bias+relu+split -> frags ; ... ; stencil3+mean -> partials ; readout
// GEMM: mma.sync m16n8k16 bf16, 3-pass split (D = Ah*Bh + Ah*Bl + Al*Bh),
//       operands via __ldg from fragment-ordered global buffers.
// Frag layout per (b, 128n-tile, 64k-chunk): 64 rows x 64 words;
//   word = ((n>>3)*4 + ks)*64 + (n&7)*8 + sidx, sidx = kb<8 ? kb : kb-7
//   word content = pack_bf16(k=kb, k=kb+1)      [verified rounds 8-15]
// ---------------------------------------------------------------------------

#define B_  16
#define N_  4096

typedef unsigned long long u64;

__device__ float    g_sup[B_ * 128 * N_];            // 33.5 MB raw support
__device__ uint32_t g_xh0[B_ * 32 * 2 * 4096];       // frag buffers (hi/lo x2)
__device__ uint32_t g_xl0[B_ * 32 * 2 * 4096];
__device__ uint32_t g_xh1[B_ * 32 * 2 * 4096];
__device__ uint32_t g_xl1[B_ * 32 * 2 * 4096];
__device__ float    g_part[512 * 4 * 128];           // 512 tiles x 4 n-quarters
__device__ uint32_t g_wfh[20480];                    // W frags hi (g1|g2|g3)
__device__ uint32_t g_wfl[20480];                    // W frags lo

__device__ __forceinline__ void fma2(u64& d, u64 a, u64 b) {
    asm("fma.rn.f32x2 %0, %1, %2, %0;" : "+l"(d) : "l"(a), "l"(b));
}
__device__ __forceinline__ u64 pack2(float lo, float hi) {
    u64 r; asm("mov.b64 %0, {%1, %2};" : "=l"(r) : "f"(lo), "f"(hi)); return r;
}
__device__ __forceinline__ float2 unpack2(u64 v) {
    float2 f; asm("mov.b64 {%0, %1}, %2;" : "=f"(f.x), "=f"(f.y) : "l"(v)); return f;
}
__device__ __forceinline__ float recip_deg(int deg) {
    return deg == 4 ? 0.2499999375f : (deg == 3 ? 0.3333332222f : 0.4999997500f);
}
__device__ __forceinline__ uint32_t pack_bf16(__nv_bfloat16 a, __nv_bfloat16 b) {
    return (uint32_t)__bfloat16_as_ushort(a) | ((uint32_t)__bfloat16_as_ushort(b) << 16);
}
__device__ __forceinline__ uint32_t split_pack(float v0, float v1, uint32_t& lo) {
    const __nv_bfloat16 h0 = __float2bfloat16(v0);
    const __nv_bfloat16 h1 = __float2bfloat16(v1);
    lo = pack_bf16(__float2bfloat16(v0 - __bfloat162float(h0)),
                   __float2bfloat16(v1 - __bfloat162float(h1)));
    return pack_bf16(h0, h1);
}
__device__ __forceinline__ void mma_bf16(float* c, const uint32_t* a, uint32_t b0, uint32_t b1) {
    asm volatile(
        "mma.sync.aligned.m16n8k16.row.col.f32.bf16.bf16.f32 "
        "{%0,%1,%2,%3}, {%4,%5,%6,%7}, {%8,%9}, {%0,%1,%2,%3};"
        : "+f"(c[0]), "+f"(c[1]), "+f"(c[2]), "+f"(c[3])
        : "r"(a[0]), "r"(a[1]), "r"(a[2]), "r"(a[3]), "r"(b0), "r"(b1));
}
__device__ __forceinline__ void cp16(uint32_t daddr, const void* g, int sz) {
    asm volatile("cp.async.cg.shared.global [%0], [%1], 16, %2;"
                 :: "r"(daddr), "l"(g), "r"(sz) : "memory");
}
#define CP_COMMIT() asm volatile("cp.async.commit_group;" ::: "memory")
#define CP_WAIT0()  asm volatile("cp.async.wait_group 0;" ::: "memory")

// ---------------------------------------------------------------------------
// Fused embed MLP + wsplit. Blocks [0,512): embed; blocks [512,592): wsplit.
// (unchanged from round 15 -- verified correct)
// ---------------------------------------------------------------------------
#define SMEM_EMB 61440

__global__ void __launch_bounds__(256, 3)
embed_ws_kernel(const float* __restrict__ obs,
                const float* __restrict__ w1, const float* __restrict__ b1,
                const float* __restrict__ w2, const float* __restrict__ b2,
                const float* __restrict__ g1w, const float* __restrict__ g2w,
                const float* __restrict__ g3w,
                uint32_t* __restrict__ xh, uint32_t* __restrict__ xl,
                uint32_t* __restrict__ wfh, uint32_t* __restrict__ wfl)
{
    const int tid = threadIdx.x;

    if (blockIdx.x >= 512) {
        const int idx = (blockIdx.x - 512) * 256 + tid;   // 0..20479
        const float* W; int base;
        if (idx < 4096)       { W = g1w; base = 0; }
        else if (idx < 12288) { W = g2w; base = 4096; }
        else                  { W = g3w; base = 12288; }
        const int r = idx - base;
        const int chunk = r >> 12;
        const int w = r & 4095;
        const int lane4 = w & 127, ksI = (w >> 7) & 3, t = (w >> 9) & 1, wq = (w >> 10) & 3;
        const int lane = lane4 >> 2, j = lane4 & 3;
        const int grp = lane >> 2, tig = lane & 3;
        const int d = wq * 32 + t * 16 + grp + (j & 1) * 8;
        const int kg = chunk * 64 + ksI * 16 + tig * 2 + (j >> 1) * 8;
        const float w0 = W[kg * 128 + d];
        const float w1v = W[(kg + 1) * 128 + d];
        uint32_t lo0; const uint32_t hi0 = split_pack(w0, w1v, lo0);
        wfh[idx] = hi0; wfl[idx] = lo0;
        return;
    }

    extern __shared__ __align__(16) float esm[];
    float* Xs  = esm;
    float* W1s = esm + 2048;
    float* W2s = esm + 3072;
    float* Hs  = esm + 7168;
    float* Hstage = esm;

    uint32_t sb;
    asm("{ .reg .u64 t; cvta.to.shared.u64 t, %1; cvt.u32.u64 %0, t; }" : "=r"(sb) : "l"(esm));

    const int tx = tid & 15, ty = tid >> 4;
    const int m0 = blockIdx.x * 128;
    const int b  = m0 >> 12, n0 = m0 & (N_ - 1);
    const int bt = m0 >> 7;
    const float* xb = obs + (size_t)b * 16 * N_ + n0;

    {
        const int i0 = tid, i1 = tid + 256;
        cp16(sb + (uint32_t)(((i0 >> 5) * 128 + (i0 & 31) * 4) * 4),
             reinterpret_cast<const float4*>(xb + (size_t)(i0 >> 5) * N_) + (i0 & 31), 16);
        cp16(sb + (uint32_t)(((i1 >> 5) * 128 + (i1 & 31) * 4) * 4),
             reinterpret_cast<const float4*>(xb + (size_t)(i1 >> 5) * N_) + (i1 & 31), 16);
        cp16(sb + (uint32_t)((2048 + tid * 4) * 4), reinterpret_cast<const float4*>(w1) + tid, 16);
#pragma unroll
        for (int i = 0; i < 4; i++)
            cp16(sb + (uint32_t)((3072 + (i * 256 + tid) * 4) * 4),
                 reinterpret_cast<const float4*>(w2) + i * 256 + tid, 16);
    }
    CP_COMMIT();
    CP_WAIT0();
    __syncthreads();

    u64 acc[4][4];
#pragma unroll
    for (int dd = 0; dd < 4; dd++) {
        const float bv = b1[ty * 4 + dd];
        const u64 bp = pack2(bv, bv);
#pragma unroll
        for (int j = 0; j < 4; j++) acc[dd][j] = bp;
    }
#pragma unroll
    for (int k = 0; k < 16; k++) {
        const ulonglong2 a01 = *reinterpret_cast<const ulonglong2*>(&Xs[k * 128 + tx * 8]);
        const ulonglong2 a23 = *reinterpret_cast<const ulonglong2*>(&Xs[k * 128 + tx * 8 + 4]);
        const u64 a[4] = { a01.x, a01.y, a23.x, a23.y };
        const float4 w = *reinterpret_cast<const float4*>(&W1s[k * 64 + ty * 4]);
        const float wv[4] = { w.x, w.y, w.z, w.w };
#pragma unroll
        for (int dd = 0; dd < 4; dd++) {
            const u64 wd = pack2(wv[dd], wv[dd]);
#pragma unroll
            for (int j = 0; j < 4; j++) fma2(acc[dd][j], wd, a[j]);
        }
    }
#pragma unroll
    for (int dd = 0; dd < 4; dd++) {
        float* hr = &Hs[(ty * 4 + dd) * 128 + tx * 8];
#pragma unroll
        for (int j = 0; j < 4; j += 2) {
            const float2 p0 = unpack2(acc[dd][j]), p1 = unpack2(acc[dd][j + 1]);
            float4 o = { fmaxf(p0.x, 0.f), fmaxf(p0.y, 0.f), fmaxf(p1.x, 0.f), fmaxf(p1.y, 0.f) };
            *reinterpret_cast<float4*>(hr + j * 2) = o;
        }
    }
    __syncthreads();

    u64 acc2[4][4];
#pragma unroll
    for (int dd = 0; dd < 4; dd++) {
        const float bv = b2[ty * 4 + dd];
        const u64 bp = pack2(bv, bv);
#pragma unroll
        for (int j = 0; j < 4; j++) acc2[dd][j] = bp;
    }
#pragma unroll 4
    for (int k = 0; k < 64; k++) {
        const ulonglong2 a01 = *reinterpret_cast<const ulonglong2*>(&Hs[k * 128 + tx * 8]);
        const ulonglong2 a23 = *reinterpret_cast<const ulonglong2*>(&Hs[k * 128 + tx * 8 + 4]);
        const u64 a[4] = { a01.x, a01.y, a23.x, a23.y };
        const float4 w = *reinterpret_cast<const float4*>(&W2s[k * 64 + ty * 4]);
        const float wv[4] = { w.x, w.y, w.z, w.w };
#pragma unroll
        for (int dd = 0; dd < 4; dd++) {
            const u64 wd = pack2(wv[dd], wv[dd]);
#pragma unroll
            for (int j = 0; j < 4; j++) fma2(acc2[dd][j], wd, a[j]);
        }
    }

    const int n_loc = tid >> 1, ksh = tid & 1;
#pragma unroll
    for (int h = 0; h < 2; h++) {
        __syncthreads();
        if ((ty >> 3) == h) {
            const int dl0 = (ty & 7) * 4;
#pragma unroll
            for (int dd = 0; dd < 4; dd++) {
                float* hr = &Hstage[(dl0 + dd) * 128 + tx * 8];
#pragma unroll
                for (int j = 0; j < 4; j++) {
                    const float2 p = unpack2(acc2[dd][j]);
                    hr[j * 2]     = fmaxf(p.x, 0.f);
                    hr[j * 2 + 1] = fmaxf(p.y, 0.f);
                }
            }
        }
        __syncthreads();

        const int ks = h * 2 + ksh;
        uint32_t wh[8], wl[8];
#pragma unroll
        for (int p = 0; p < 8; p++) {
            const float v0 = Hstage[(ksh * 16 + 2 * p) * 128 + n_loc];
            const float v1 = Hstage[(ksh * 16 + 2 * p + 1) * 128 + n_loc];
            const int sidx = (2 * p < 8) ? 2 * p : 2 * p - 7;
            wh[sidx] = split_pack(v0, v1, wl[sidx]);
        }
        const size_t base = (size_t)bt * 4096 + (size_t)(((n_loc >> 3) * 4 + ks) * 64 + (n_loc & 7) * 8);
        uint4 a0 = { wh[0], wh[1], wh[2], wh[3] }, a1 = { wh[4], wh[5], wh[6], wh[7] };
        uint4 c0 = { wl[0], wl[1], wl[2], wl[3] }, c1 = { wl[4], wl[5], wl[6], wl[7] };
        *reinterpret_cast<uint4*>(xh + base)     = a0;
        *reinterpret_cast<uint4*>(xh + base + 4) = a1;
        *reinterpret_cast<uint4*>(xl + base)     = c0;
        *reinterpret_cast<uint4*>(xl + base + 4) = c1;
    }
}

// ---------------------------------------------------------------------------
// GEMM: support[b][128 d][n] = W^T(128xK) * X(Kxn). No smem, no barriers.
// B-frag loads of a slice hoisted into register arrays before the MMA burst.
// ---------------------------------------------------------------------------
template <int K>
__global__ void __launch_bounds__(256, 2)
gemm_kernel(const uint32_t* __restrict__ xh, const uint32_t* __restrict__ xl,
            const uint32_t* __restrict__ wfh, const uint32_t* __restrict__ wfl,
            float* __restrict__ sup)
{
    constexpr int NCH = K / 64;
    const int tid = threadIdx.x;
    const int wid = tid >> 5, lane = tid & 31;
    const int grp = lane >> 2, tig = lane & 3;
    const int wq = wid & 3, nh = wid >> 2;
    const int bt = blockIdx.x;
    const int b = bt >> 5, n0 = (bt & 31) * 128;
    const uint32_t* bhp = xh + (size_t)bt * NCH * 4096;
    const uint32_t* blp = xl + (size_t)bt * NCH * 4096;

    float acc[2][8][4];
#pragma unroll
    for (int t = 0; t < 2; t++)
#pragma unroll
        for (int c = 0; c < 8; c++)
#pragma unroll
            for (int j = 0; j < 4; j++) acc[t][c][j] = 0.f;

#pragma unroll
    for (int wg = 0; wg < K / 16; wg++) {
        const int chunk = wg >> 2, ks = wg & 3;
        uint32_t ah[2][4], al[2][4];
#pragma unroll
        for (int t = 0; t < 2; t++) {
            const int fo = chunk * 4096 + ((wq * 2 + t) * 4 + ks) * 128 + lane * 4;
            const uint4 vh = __ldg(reinterpret_cast<const uint4*>(&wfh[fo]));
            const uint4 vl = __ldg(reinterpret_cast<const uint4*>(&wfl[fo]));
            ah[t][0] = vh.x; ah[t][1] = vh.y; ah[t][2] = vh.z; ah[t][3] = vh.w;
            al[t][0] = vl.x; al[t][1] = vl.y; al[t][2] = vl.z; al[t][3] = vl.w;
        }
        // Hoist all B loads of the slice (maximize MLP)
        uint2 bh[8], bl[8];
#pragma unroll
        for (int c = 0; c < 8; c++) {
            const int off = chunk * 4096 + ((nh * 8 + c) * 4 + ks) * 64 + lane * 2;
            bh[c] = __ldg(reinterpret_cast<const uint2*>(bhp + off));
            bl[c] = __ldg(reinterpret_cast<const uint2*>(blp + off));
        }
#pragma unroll
        for (int c = 0; c < 8; c++) {
            mma_bf16(acc[0][c], ah[0], bh[c].x, bh[c].y);
            mma_bf16(acc[0][c], ah[0], bl[c].x, bl[c].y);
            mma_bf16(acc[0][c], al[0], bh[c].x, bh[c].y);
            mma_bf16(acc[1][c], ah[1], bh[c].x, bh[c].y);
            mma_bf16(acc[1][c], ah[1], bl[c].x, bl[c].y);
            mma_bf16(acc[1][c], al[1], bh[c].x, bh[c].y);
        }
    }

    const int d0 = wq * 32 + grp;
    float* ob = sup + (size_t)b * 128 * N_ + n0;
#pragma unroll
    for (int t = 0; t < 2; t++) {
        float* r0 = ob + (size_t)(d0 + t * 16) * N_;
        float* r1 = r0 + (size_t)8 * N_;
#pragma unroll
        for (int c = 0; c < 8; c++) {
            const int nn = nh * 64 + c * 8 + tig * 2;
            float2 v0 = { acc[t][c][0], acc[t][c][1] };
            float2 v1 = { acc[t][c][2], acc[t][c][3] };
            *reinterpret_cast<float2*>(r0 + nn) = v0;
            *reinterpret_cast<float2*>(r1 + nn) = v1;
        }
    }
}

// ---------------------------------------------------------------------------
// Stencil pass v2: unit = (1 n x 16 d). Warp = 32 consecutive n, same ksg ->
// coalesced row reads AND contiguous frag-row writes (8 consecutive n span a
// full 64-word frag row). Grid 2048 CTAs x 256 thr = 1 unit/thread.
// MEAN: warp shfl-reduce over 32 n; part[bt*4 + n/32][128].
// ---------------------------------------------------------------------------
template <bool MEAN>
__global__ void __launch_bounds__(256)
stencil_kernel(const float* __restrict__ sup, const float* __restrict__ bias,
               uint32_t* __restrict__ oh, uint32_t* __restrict__ ol,
               float* __restrict__ part)
{
    const int gid = blockIdx.x * 256 + threadIdx.x;
    const int bt  = gid >> 10;                 // (b, tile)
    const int u   = gid & 1023;
    const int n   = u & 127;                   // n within tile
    const int ksg = u >> 7;                    // 0..7 -> 16-d group
    const int d0  = ksg * 16;
    const int b = bt >> 5, tile = bt & 31;

    const int gn = tile * 128 + n;
    const int gi = gn >> 6, gj = gn & 63;
    const bool upv = gi > 0, dnv = gi < 63;
    const bool lfv = gj != 0, rtv = gj != 63;
    const int dg = (upv ? 1 : 0) + (dnv ? 1 : 0) + (lfv ? 1 : 0) + (rtv ? 1 : 0);
    const float rd = recip_deg(dg);
    const float sn = (float)dg * rd;
    const float* sbp = sup + ((size_t)b * 128 + d0) * N_ + gn;

    float y[16];
#pragma unroll
    for (int d = 0; d < 16; d++) {
        const float* row = sbp + (size_t)d * N_;
        const float up = upv ? __ldg(row - 64) : 0.f;
        const float dn = dnv ? __ldg(row + 64) : 0.f;
        const float lf = lfv ? __ldg(row - 1)  : 0.f;
        const float rt = rtv ? __ldg(row + 1)  : 0.f;
        const float bv = __ldg(&bias[d0 + d]);
        y[d] = fmaxf(fmaf(sn, bv, (up + dn + lf + rt) * rd), 0.f);
    }

    if (!MEAN) {
        const int chunk = ksg >> 2, ks2 = ksg & 3;
        uint32_t wh[8], wl[8];
#pragma unroll
        for (int p = 0; p < 8; p++) {
            const int sidx = (2 * p < 8) ? 2 * p : 2 * p - 7;
            wh[sidx] = split_pack(y[2 * p], y[2 * p + 1], wl[sidx]);
        }
        const size_t base = ((size_t)bt * 2 + chunk) * 4096
                          + (size_t)(((n >> 3) * 4 + ks2) * 64 + (n & 7) * 8);
        uint4 h0 = { wh[0], wh[1], wh[2], wh[3] };
        uint4 h1 = { wh[4], wh[5], wh[6], wh[7] };
        uint4 l0 = { wl[0], wl[1], wl[2], wl[3] };
        uint4 l1 = { wl[4], wl[5], wl[6], wl[7] };
        *reinterpret_cast<uint4*>(oh + base)     = h0;
        *reinterpret_cast<uint4*>(oh + base + 4) = h1;
        *reinterpret_cast<uint4*>(ol + base)     = l0;
        *reinterpret_cast<uint4*>(ol + base + 4) = l1;
    } else {
        // warp = 32 consecutive n (same ksg): full-warp reduce per d
#pragma unroll
        for (int d = 0; d < 16; d++) {
            float v = y[d];
            v += __shfl_xor_sync(0xffffffffu, v, 1);
            v += __shfl_xor_sync(0xffffffffu, v, 2);
            v += __shfl_xor_sync(0xffffffffu, v, 4);
            v += __shfl_xor_sync(0xffffffffu, v, 8);
            v += __shfl_xor_sync(0xffffffffu, v, 16);
            y[d] = v;
        }
        if ((n & 31) == 0) {
            float* pp = part + ((size_t)bt * 4 + (n >> 5)) * 128 + d0;
#pragma unroll
            for (int d = 0; d < 16; d++) pp[d] = y[d];
        }
    }
}

// ---------------------------------------------------------------------------
// Readout: g[b] = mean of 128 partials; out = relu(relu(g r1 + b1) r2 + b2)
// ---------------------------------------------------------------------------
__global__ void __launch_bounds__(256)
readout_kernel(const float* __restrict__ part,
               const float* __restrict__ r1w, const float* __restrict__ r1b,
               const float* __restrict__ r2w, const float* __restrict__ r2b,
               float* __restrict__ out)
{
    __shared__ float gs[128];
    __shared__ float ts[256];
    const int b = blockIdx.x, t = threadIdx.x;

    if (t < 128) {
        float s = 0.f;
        const float* p = part + (size_t)b * 128 * 128 + t;
#pragma unroll
        for (int k = 0; k < 128; k++) s += p[k * 128];
        gs[t] = s * (1.0f / (float)N_);
    }
    __syncthreads();

    float a1 = r1b[t];
#pragma unroll 8
    for (int k = 0; k < 128; k++) a1 = fmaf(gs[k], r1w[k * 256 + t], a1);
    ts[t] = fmaxf(a1, 0.f);
    __syncthreads();

    float a2 = r2b[t];
#pragma unroll 8
    for (int k = 0; k < 256; k++) a2 = fmaf(ts[k], r2w[k * 256 + t], a2);
    out[b * 256 + t] = fmaxf(a2, 0.f);
}

// ---------------------------------------------------------------------------
extern "C" void kernel_launch(void* const* d_in, const int* in_sizes, int n_in,
                              void* d_out, int out_size)
{
    const float* obs  = (const float*)d_in[0];
    const float* e1_w = (const float*)d_in[1];
    const float* e1_b = (const float*)d_in[2];
    const float* e2_w = (const float*)d_in[3];
    const float* e2_b = (const float*)d_in[4];
    const float* g1_w = (const float*)d_in[5];
    const float* g1_b = (const float*)d_in[6];
    const float* g2_w = (const float*)d_in[7];
    const float* g2_b = (const float*)d_in[8];
    const float* g3_w = (const float*)d_in[9];
    const float* g3_b = (const float*)d_in[10];
    const float* r1_w = (const float*)d_in[11];
    const float* r1_b = (const float*)d_in[12];
    const float* r2_w = (const float*)d_in[13];
    const float* r2_b = (const float*)d_in[14];
    float* out = (float*)d_out;

    float *sup, *part;
    uint32_t *xh0, *xl0, *xh1, *xl1, *wfh, *wfl;
    cudaGetSymbolAddress((void**)&sup,  g_sup);
    cudaGetSymbolAddress((void**)&part, g_part);
    cudaGetSymbolAddress((void**)&xh0,  g_xh0);
    cudaGetSymbolAddress((void**)&xl0,  g_xl0);
    cudaGetSymbolAddress((void**)&xh1,  g_xh1);
    cudaGetSymbolAddress((void**)&xl1,  g_xl1);
    cudaGetSymbolAddress((void**)&wfh,  g_wfh);
    cudaGetSymbolAddress((void**)&wfl,  g_wfl);

    cudaFuncSetAttribute(embed_ws_kernel, cudaFuncAttributeMaxDynamicSharedMemorySize, SMEM_EMB);

    embed_ws_kernel<<<592, 256, SMEM_EMB>>>(obs, e1_w, e1_b, e2_w, e2_b,
                                            g1_w, g2_w, g3_w, xh0, xl0, wfh, wfl);
    gemm_kernel<64><<<512, 256>>>(xh0, xl0, wfh, wfl, sup);
    stencil_kernel<false><<<2048, 256>>>(sup, g1_b, xh1, xl1, nullptr);
    gemm_kernel<128><<<512, 256>>>(xh1, xl1, wfh + 4096, wfl + 4096, sup);
    stencil_kernel<false><<<2048, 256>>>(sup, g2_b, xh0, xl0, nullptr);
    gemm_kernel<128><<<512, 256>>>(xh0, xl0, wfh + 12288, wfl + 12288, sup);
    stencil_kernel<true><<<2048, 256>>>(sup, g3_b, nullptr, nullptr, part);
    readout_kernel<<<B_, 256>>>(part, r1_w, r1_b, r2_w, r2_b, out);
}